// round 12
// baseline (speedup 1.0000x reference)
#include <cuda_runtime.h>
#include <cstdint>

// DynamicWeightAttention via mma.sync tf32.
// Balanced warp tiling: each warp PAIR owns 32 rows; within the pair,
// warp 'sub' owns 32 of the 64 hidden dims (2 mt-slabs). Partial scores are
// exchanged via smem. All synchronization is 64-thread named barriers
// (bar.sync 1+pair, 64) -> no block-wide convoy; single-buffered smem.
// LN folded into epilogue; softmax over 16 consecutive rows.

#define C_FEAT 32
#define HID    64
#define TILE_M 128
#define GRID_B 2048
#define XROW   36                 // padded words per row (conflict-free)

__device__ float  g_W[HID * C_FEAT];  // [d][k] = tf32(gamma[k]*w1[k][d])
__device__ float4 g_p4[HID];          // {u_d, v_d, w2_d, 0}
__device__ float  g_b2;

__device__ __forceinline__ uint32_t tf32r(float x) {
    uint32_t r; asm("cvt.rna.tf32.f32 %0, %1;" : "=r"(r) : "f"(x)); return r;
}
__device__ __forceinline__ float tanha(float x) {
    float r; asm("tanh.approx.f32 %0, %1;" : "=f"(r) : "f"(x)); return r;
}
__device__ __forceinline__ void mma8(float& d0, float& d1, float& d2, float& d3,
                                     uint32_t a0, uint32_t a1, uint32_t a2, uint32_t a3,
                                     uint32_t b0, uint32_t b1) {
    asm("mma.sync.aligned.m16n8k8.row.col.f32.tf32.tf32.f32 "
        "{%0,%1,%2,%3}, {%4,%5,%6,%7}, {%8,%9}, {%0,%1,%2,%3};"
        : "+f"(d0), "+f"(d1), "+f"(d2), "+f"(d3)
        : "r"(a0), "r"(a1), "r"(a2), "r"(a3), "r"(b0), "r"(b1));
}
__device__ __forceinline__ void barp(int id) {
    asm volatile("bar.sync %0, 64;" :: "r"(id) : "memory");
}

__global__ void prep_kernel(const float* __restrict__ gamma, const float* __restrict__ beta,
                            const float* __restrict__ w1,    const float* __restrict__ b1,
                            const float* __restrict__ w2,    const float* __restrict__ b2) {
    int d = threadIdx.x;
    if (d >= HID) return;
    float u = 0.f, v = 0.f;
    for (int k = 0; k < C_FEAT; k++) {
        float wp = __uint_as_float(tf32r(gamma[k] * w1[k * HID + d]));
        g_W[d * C_FEAT + k] = wp;
        u += wp;
        v += beta[k] * w1[k * HID + d];
    }
    g_p4[d] = make_float4(u, v + b1[d], w2[d], 0.f);
    if (d == 0) g_b2 = b2[0];
}

__global__ __launch_bounds__(256, 3)
void dwa_kernel(const float* __restrict__ dyn, const float* __restrict__ stat,
                float* __restrict__ out, int tiles_per_block) {
    __shared__ uint32_t xs[TILE_M * XROW];            // 18 KB (single buffer)
    __shared__ __align__(16) uint4  aw[16][32];       // 8 KB A-frag table
    __shared__ __align__(16) float4 p4s[HID];         // 1 KB
    __shared__ float means[TILE_M], rstds[TILE_M];    // 1 KB
    __shared__ float psum[2][TILE_M];                 // 1 KB partial scores
    __shared__ float b2s;

    const int tid   = threadIdx.x;
    const int lane  = tid & 31;
    const int wid   = tid >> 5;
    const int g     = lane >> 2;      // groupID
    const int c     = lane & 3;       // threadID_in_group
    const int lrow  = tid >> 1;       // staged block-local row (0..127)
    const int half  = tid & 1;        // 8-col slice of dyn AND of stat
    const int pairI = wid >> 1;       // warp pair 0..3 (owns rows 32*pairI..+31)
    const int sub   = wid & 1;        // hidden-dim half: d in [32*sub, 32*sub+32)
    const int prow0 = pairI * 32;
    const int barid = 1 + pairI;

    if (tid < HID) p4s[tid] = g_p4[tid];
    if (tid == 0)  b2s = g_b2;
    // A-fragment table: slab s=mt*4+ks, lane l=(gg,cc)
    for (int e = tid; e < 512; e += 256) {
        int sI = e >> 5, l = e & 31;
        int mt = sI >> 2, ks = sI & 3;
        int gg = l >> 2, cc = l & 3;
        int d0 = mt * 16 + gg, k0 = ks * 8 + cc;
        uint4 v;
        v.x = __float_as_uint(g_W[d0 * 32 + k0]);
        v.y = __float_as_uint(g_W[(d0 + 8) * 32 + k0]);
        v.z = __float_as_uint(g_W[d0 * 32 + k0 + 4]);
        v.w = __float_as_uint(g_W[(d0 + 8) * 32 + k0 + 4]);
        aw[sI][l] = v;
    }
    __syncthreads();

    for (int it = 0; it < tiles_per_block; it++) {
        const long rbase = ((long)blockIdx.x * tiles_per_block + it) * TILE_M;
        const long row   = rbase + lrow;

        // ---- stage half a row (regs only until the stores) ----
        uint32_t xw[16];
        float s = 0.f, ss = 0.f;
        {
            const float4* d4 = (const float4*)dyn + row * 4 + half * 2;
            const float4* s4 = (const float4*)stat + (long)(row & 4095) * 4 + half * 2;
            #pragma unroll
            for (int k = 0; k < 2; k++) {
                float4 v = d4[k];
                s += v.x + v.y + v.z + v.w;
                ss += v.x*v.x + v.y*v.y + v.z*v.z + v.w*v.w;
                xw[4*k] = tf32r(v.x); xw[4*k+1] = tf32r(v.y);
                xw[4*k+2] = tf32r(v.z); xw[4*k+3] = tf32r(v.w);
            }
            #pragma unroll
            for (int k = 0; k < 2; k++) {
                float4 v = s4[k];
                s += v.x + v.y + v.z + v.w;
                ss += v.x*v.x + v.y*v.y + v.z*v.z + v.w*v.w;
                xw[8+4*k] = tf32r(v.x); xw[8+4*k+1] = tf32r(v.y);
                xw[8+4*k+2] = tf32r(v.z); xw[8+4*k+3] = tf32r(v.w);
            }
        }
        s  += __shfl_xor_sync(0xffffffffu, s, 1);
        ss += __shfl_xor_sync(0xffffffffu, ss, 1);
        const float mean = s * (1.0f / C_FEAT);
        const float var  = ss * (1.0f / C_FEAT) - mean * mean;
        const float rstd = rsqrtf(var + 1e-4f);

        means[lrow] = mean;   // safe vs prev iter: readers passed BAR2(it-1)
        rstds[lrow] = rstd;
        // k-reordered stores: word k -> p = (k&3)*8 + (k>>3)*2 + ((k>>2)&1)
        {
            uint32_t* xr = xs + lrow * XROW;
            #pragma unroll
            for (int j = 0; j < 4; j++) {
                *(uint2*)(xr + j * 8 + 2 * half)     = make_uint2(xw[j],     xw[j + 4]);
                *(uint2*)(xr + j * 8 + 4 + 2 * half) = make_uint2(xw[8 + j], xw[12 + j]);
            }
        }
        barp(barid);   // BAR1: pair's 32 rows staged

        // ---- b fragments: 4 nt-row-groups x 2 LDS.128 ----
        uint4 blo[4], bhi[4];
        #pragma unroll
        for (int nt = 0; nt < 4; nt++) {
            int browL = prow0 + 8 * nt + g;
            const uint4* q = (const uint4*)(xs + browL * XROW + c * 8);
            blo[nt] = q[0]; bhi[nt] = q[1];
        }

        // ---- MMA + partial epilogue, phased over 2 mt-slabs (acc = 16 regs) ----
        float sc[4][2];
        #pragma unroll
        for (int nt = 0; nt < 4; nt++) { sc[nt][0] = 0.f; sc[nt][1] = 0.f; }

        #pragma unroll
        for (int mtp = 0; mtp < 2; mtp++) {
            float acc[4][4];
            #pragma unroll
            for (int nt = 0; nt < 4; nt++)
                #pragma unroll
                for (int q = 0; q < 4; q++) acc[nt][q] = 0.f;

            #pragma unroll
            for (int ks = 0; ks < 4; ks++) {
                uint4 a = aw[(2 * sub + mtp) * 4 + ks][lane];
                #pragma unroll
                for (int nt = 0; nt < 4; nt++) {
                    uint32_t b0 = (ks == 0) ? blo[nt].x : (ks == 1) ? blo[nt].z
                                : (ks == 2) ? bhi[nt].x : bhi[nt].z;
                    uint32_t b1 = (ks == 0) ? blo[nt].y : (ks == 1) ? blo[nt].w
                                : (ks == 2) ? bhi[nt].y : bhi[nt].w;
                    mma8(acc[nt][0], acc[nt][1], acc[nt][2], acc[nt][3],
                         a.x, a.y, a.z, a.w, b0, b1);
                }
            }
            #pragma unroll
            for (int hh = 0; hh < 2; hh++) {
                int d = 32 * sub + 16 * mtp + 8 * hh + g;
                float4 p = p4s[d];          // {u, v, w2}
                #pragma unroll
                for (int nt = 0; nt < 4; nt++) {
                    #pragma unroll
                    for (int i = 0; i < 2; i++) {
                        int r = prow0 + 8 * nt + 2 * c + i;
                        float t1 = fmaf(-means[r], p.x, acc[nt][2*hh + i]);
                        float h  = fmaf(t1, rstds[r], p.y);
                        sc[nt][i] = fmaf(tanha(h), p.z, sc[nt][i]);
                    }
                }
            }
        }
        // reduce over g-lanes; then publish this warp's 32-dim partial
        #pragma unroll
        for (int o = 4; o <= 16; o <<= 1)
            #pragma unroll
            for (int nt = 0; nt < 4; nt++)
                #pragma unroll
                for (int i = 0; i < 2; i++)
                    sc[nt][i] += __shfl_xor_sync(0xffffffffu, sc[nt][i], o);
        if (g == 0) {
            #pragma unroll
            for (int nt = 0; nt < 4; nt++)
                #pragma unroll
                for (int i = 0; i < 2; i++)
                    psum[sub][prow0 + 8 * nt + 2 * c + i] = sc[nt][i];
        }
        barp(barid);   // BAR2: both halves' partials visible

        // ---- finalize: warp 'sub' owns pair rows 16*sub..+15 ----
        const float b2v = b2s;
        float scf[2][2];
        #pragma unroll
        for (int np = 0; np < 2; np++)
            #pragma unroll
            for (int i = 0; i < 2; i++) {
                int r = prow0 + 16 * sub + 8 * np + 2 * c + i;
                scf[np][i] = psum[0][r] + psum[1][r] + b2v;
            }
        float m = fmaxf(fmaxf(scf[0][0], scf[0][1]), fmaxf(scf[1][0], scf[1][1]));
        m = fmaxf(m, __shfl_xor_sync(0xffffffffu, m, 1));
        m = fmaxf(m, __shfl_xor_sync(0xffffffffu, m, 2));
        float e[2][2], esum = 0.f;
        #pragma unroll
        for (int np = 0; np < 2; np++)
            #pragma unroll
            for (int i = 0; i < 2; i++) { e[np][i] = __expf(scf[np][i] - m); esum += e[np][i]; }
        esum += __shfl_xor_sync(0xffffffffu, esum, 1);
        esum += __shfl_xor_sync(0xffffffffu, esum, 2);
        const float inv = 1.0f / esum;

        if (g == 0) {
            #pragma unroll
            for (int np = 0; np < 2; np++) {
                float2 o2 = make_float2(e[np][0] * inv, e[np][1] * inv);
                *(float2*)(out + rbase + prow0 + 16 * sub + 8 * np + 2 * c) = o2;
            }
        }
    }
}

extern "C" void kernel_launch(void* const* d_in, const int* in_sizes, int n_in,
                              void* d_out, int out_size) {
    const float* dyn   = (const float*)d_in[0];
    const float* stat  = (const float*)d_in[1];
    const float* gamma = (const float*)d_in[2];
    const float* beta  = (const float*)d_in[3];
    const float* w1    = (const float*)d_in[4];
    const float* b1    = (const float*)d_in[5];
    const float* w2    = (const float*)d_in[6];
    const float* b2    = (const float*)d_in[7];
    float* out = (float*)d_out;

    const long nrows = (long)in_sizes[0] / 16;      // 4,194,304
    const long tiles = nrows / TILE_M;              // 32,768
    const int  tpb   = (int)(tiles / GRID_B);       // 16

    prep_kernel<<<1, 64>>>(gamma, beta, w1, b1, w2, b2);
    dwa_kernel<<<GRID_B, 256>>>(dyn, stat, out, tpb);
}